// round 7
// baseline (speedup 1.0000x reference)
#include <cuda_runtime.h>
#include <math.h>

#define DIN 4096
#define NH  4096

// Two warps per hidden element j; each warp handles half the columns
// (2048 of 4096) for ALL seven weight rows in one merged loop:
//   x-rows: Wih[j], Wih[nh+j], Wih[2nh+j]   (o-gate aliases the g row)
//   h-rows: Whh[j], Whh[nh+j], Whh[2nh+j], Whh[3nh+j]
// Reference quirk: Wio == Wih[2nh:3nh], so z_o reuses the g-row x-dot;
// Wih[3nh:4nh] is never read. 448 MB total DRAM = the floor.
// Warp partials meet in shared memory; 2 threads/block do the gate epilogue.
// out = [it | ft | gt | ot | ct | ht], 6*NH floats.

__device__ __forceinline__ float warp_sum(float v) {
    #pragma unroll
    for (int off = 16; off > 0; off >>= 1)
        v += __shfl_xor_sync(0xFFFFFFFFu, v, off);
    return v;
}

__device__ __forceinline__ float sigmoidf_(float v) {
    return 1.0f / (1.0f + __expf(-v));
}

__device__ __forceinline__ float dot4(const float4 w, const float4 v) {
    return w.x * v.x + w.y * v.y + w.z * v.z + w.w * v.w;
}

__global__ __launch_bounds__(128) void lstm_fused_kernel(
    const float* __restrict__ x,
    const float* __restrict__ h,
    const float* __restrict__ c,
    const float* __restrict__ Wih,
    const float* __restrict__ Whh,
    const float* __restrict__ bih,
    const float* __restrict__ bhh,
    float* __restrict__ out)
{
    __shared__ float partial[4][7];   // [warp_in_block][accumulator]

    const int wib  = threadIdx.x >> 5;      // 0..3
    const int lane = threadIdx.x & 31;
    const int elem = wib >> 1;              // 0..1 (element within block)
    const int half = wib & 1;               // 0..1 (column half)
    const int j    = blockIdx.x * 2 + elem;

    const float4* __restrict__ x4 = (const float4*)x;
    const float4* __restrict__ h4 = (const float4*)h;

    const float4* __restrict__ wi_x = (const float4*)(Wih + (size_t)j * DIN);
    const float4* __restrict__ wf_x = (const float4*)(Wih + (size_t)(NH + j) * DIN);
    const float4* __restrict__ wg_x = (const float4*)(Wih + (size_t)(2 * NH + j) * DIN);

    const float4* __restrict__ wi_h = (const float4*)(Whh + (size_t)j * NH);
    const float4* __restrict__ wf_h = (const float4*)(Whh + (size_t)(NH + j) * NH);
    const float4* __restrict__ wg_h = (const float4*)(Whh + (size_t)(2 * NH + j) * NH);
    const float4* __restrict__ wo_h = (const float4*)(Whh + (size_t)(3 * NH + j) * NH);

    // This warp's half: float4 indices [half*512, half*512+512), 16 per lane.
    const int i0   = half * (DIN / 8) + lane;
    const int iEnd = half * (DIN / 8) + (DIN / 8);

    float xi = 0.f, xf = 0.f, xg = 0.f;
    float hi = 0.f, hf = 0.f, hg = 0.f, ho = 0.f;

    // Merged loop: 9 independent float4 loads per iteration for MLP.
    #pragma unroll 2
    for (int i = i0; i < iEnd; i += 32) {
        const float4 xv = x4[i];
        const float4 hv = h4[i];
        const float4 a  = wi_x[i];
        const float4 b  = wf_x[i];
        const float4 g  = wg_x[i];
        const float4 p  = wi_h[i];
        const float4 q  = wf_h[i];
        const float4 r  = wg_h[i];
        const float4 s  = wo_h[i];
        xi += dot4(a, xv);
        xf += dot4(b, xv);
        xg += dot4(g, xv);
        hi += dot4(p, hv);
        hf += dot4(q, hv);
        hg += dot4(r, hv);
        ho += dot4(s, hv);
    }

    const float s0 = warp_sum(xi);
    const float s1 = warp_sum(xf);
    const float s2 = warp_sum(xg);
    const float s3 = warp_sum(hi);
    const float s4 = warp_sum(hf);
    const float s5 = warp_sum(hg);
    const float s6 = warp_sum(ho);

    if (lane == 0) {
        partial[wib][0] = s0;
        partial[wib][1] = s1;
        partial[wib][2] = s2;
        partial[wib][3] = s3;
        partial[wib][4] = s4;
        partial[wib][5] = s5;
        partial[wib][6] = s6;
    }
    __syncthreads();

    // Epilogue: one thread per element combines the two half-row partials.
    if (threadIdx.x < 2) {
        const int e  = threadIdx.x;
        const int je = blockIdx.x * 2 + e;
        const float* p0 = partial[2 * e];
        const float* p1 = partial[2 * e + 1];

        const float ai_x = p0[0] + p1[0];
        const float af_x = p0[1] + p1[1];
        const float ag_x = p0[2] + p1[2];
        const float ai_h = p0[3] + p1[3];
        const float af_h = p0[4] + p1[4];
        const float ag_h = p0[5] + p1[5];
        const float ao_h = p0[6] + p1[6];

        const float zi = ai_x + ai_h + __ldg(bih + je)          + __ldg(bhh + je);
        const float zf = af_x + af_h + __ldg(bih + NH + je)     + __ldg(bhh + NH + je);
        const float zg = ag_x + ag_h + __ldg(bih + 2 * NH + je) + __ldg(bhh + 2 * NH + je);
        const float zo = ag_x + ao_h + __ldg(bih + 3 * NH + je) + __ldg(bhh + 3 * NH + je);

        const float it = sigmoidf_(zi);
        const float ft = sigmoidf_(zf);
        const float gt = tanhf(zg);
        const float ot = sigmoidf_(zo);
        const float ct = ft * __ldg(c + je) + it * gt;
        const float ht = ot * tanhf(ct);

        out[je]          = it;
        out[NH + je]     = ft;
        out[2 * NH + je] = gt;
        out[3 * NH + je] = ot;
        out[4 * NH + je] = ct;
        out[5 * NH + je] = ht;
    }
}

extern "C" void kernel_launch(void* const* d_in, const int* in_sizes, int n_in,
                              void* d_out, int out_size)
{
    // metadata order: x, h, c, Wih, Whh, bih, bhh
    const float* x   = (const float*)d_in[0];
    const float* h   = (const float*)d_in[1];
    const float* c   = (const float*)d_in[2];
    const float* Wih = (const float*)d_in[3];
    const float* Whh = (const float*)d_in[4];
    const float* bih = (const float*)d_in[5];
    const float* bhh = (const float*)d_in[6];
    float* out = (float*)d_out;

    // 2 elements per 128-thread block (2 warps per element) -> 2048 blocks,
    // 8192 warps total.
    lstm_fused_kernel<<<NH / 2, 128>>>(x, h, c, Wih, Whh, bih, bhh, out);
}